// round 11
// baseline (speedup 1.0000x reference)
#include <cuda_runtime.h>
#include <cuda_bf16.h>

#define BB 4
#define SS 2048
#define DD 1024
#define HH 16
#define HD 64

typedef unsigned long long u64;
typedef unsigned int u32;
typedef unsigned short u16;

// ---- cp.async ----
#define CP16(dst, src) \
    asm volatile("cp.async.cg.shared.global [%0], [%1], 16;" :: "r"(dst), "l"(src))
#define CPC asm volatile("cp.async.commit_group;")
#define CPW(n) asm volatile("cp.async.wait_group %0;" :: "n"(n))

// ---- bf16 helpers ----
__device__ __forceinline__ u32 pkbf2(float a, float b) {
    __nv_bfloat162 t = __floats2bfloat162_rn(a, b);
    return *reinterpret_cast<u32*>(&t);
}
__device__ __forceinline__ float bf2f(u16 h) {
    __nv_bfloat16 t = *reinterpret_cast<__nv_bfloat16*>(&h);
    return __bfloat162float(t);
}
__device__ __forceinline__ void split2(float a, float b, u32& hi, u32& lo) {
    hi = pkbf2(a, b);
    float ra = a - bf2f((u16)(hi & 0xffff));
    float rb = b - bf2f((u16)(hi >> 16));
    lo = pkbf2(ra, rb);
}
__device__ __forceinline__ u32 smem_u32(const void* p) {
    u32 a;
    asm("{ .reg .u64 t; cvta.to.shared.u64 t, %1; cvt.u32.u64 %0, t; }"
        : "=r"(a) : "l"(p));
    return a;
}

// mma.sync m16n8k16 bf16
__device__ __forceinline__ void mma16816(float* d, const u32* a, const u32* b) {
    asm volatile(
        "mma.sync.aligned.m16n8k16.row.col.f32.bf16.bf16.f32 "
        "{%0,%1,%2,%3}, {%4,%5,%6,%7}, {%8,%9}, {%0,%1,%2,%3};"
        : "+f"(d[0]), "+f"(d[1]), "+f"(d[2]), "+f"(d[3])
        : "r"(a[0]), "r"(a[1]), "r"(a[2]), "r"(a[3]), "r"(b[0]), "r"(b[1]));
}

// kpair permutation within each k16 group: [0,4,1,5,2,6,3,7]
__device__ __forceinline__ int kperm(int g) {
    int j = g & 7;
    return (g & ~7) | (2 * (j & 3) + (j >> 2));
}

// ---- device scratch (all frag-ready permuted layouts) ----
__device__ uint2 d_Xi[8192 * 512];
__device__ uint2 d_Wqi[3072 * 512];
__device__ uint2 d_Woi[1024 * 512];
__device__ uint2 d_Qi[(size_t)BB * HH * SS * 32];   // permuted kpairs
__device__ uint2 d_Ki[(size_t)BB * HH * SS * 32];   // permuted kpairs
__device__ u16   d_Vt[(size_t)BB * HH * HD * 2 * SS];  // [bh][hd] interleaved {hi,lo} u32, permuted
__device__ uint2 d_Ci[8192 * 512];

// ---------------------------------------------------------------------------
// prep: fp32 -> interleaved {hi,lo}, kpair-permuted
// ---------------------------------------------------------------------------
__global__ void prep_x(const float* __restrict__ X) {
    const int N = 8192 * 512;
    for (int i = blockIdx.x * blockDim.x + threadIdx.x; i < N;
         i += gridDim.x * blockDim.x) {
        float2 v = ((const float2*)X)[i];
        u32 h, l;
        split2(v.x, v.y, h, l);
        int row = i >> 9, g = i & 511;
        d_Xi[(size_t)row * 512 + kperm(g)] = make_uint2(h, l);
    }
}

template <int NTOT>
__global__ void prep_wt(const float* __restrict__ W, uint2* __restrict__ Wt) {
    __shared__ uint2 s[32][33];
    int tx = threadIdx.x, ty = threadIdx.y;
    int n  = blockIdx.x * 32 + tx;
    int k2 = blockIdx.y * 32 + ty;
    float w0 = W[(size_t)(2 * k2) * NTOT + n];
    float w1 = W[(size_t)(2 * k2 + 1) * NTOT + n];
    u32 h, l;
    split2(w0, w1, h, l);
    s[ty][tx] = make_uint2(h, l);
    __syncthreads();
    int outn = blockIdx.x * 32 + ty;
    int outk = blockIdx.y * 32 + tx;
    Wt[(size_t)outn * 512 + kperm(outk)] = s[tx][ty];
}

// ---------------------------------------------------------------------------
// GEMM: 4-stage cp.async pipeline (proven R10). MODE 0 epilogue now writes
// Q/K permuted and V interleaved-permuted.
// ---------------------------------------------------------------------------
#define MM_SMEM (4 * 16384)

template <int MODE>
__global__ void __launch_bounds__(256, 2) mm_bf16(const uint2* __restrict__ Ai,
                                                  const uint2* __restrict__ Bi,
                                                  const float* __restrict__ bias,
                                                  float* __restrict__ outp) {
    extern __shared__ uint4 dynsm4[];
    const u32 sb = smem_u32(dynsm4);

    const int tid  = threadIdx.x;
    const int wid  = tid >> 5, lane = tid & 31;
    const int wm   = wid & 1, wn = wid >> 1;
    const int m0   = blockIdx.y * 128;
    const int n0   = blockIdx.x * 128;
    const int lq   = lane >> 2;
    const int lr   = lane & 3;

    const int srow = tid >> 1;
    const int sp   = (tid & 1) * 2;
    const uint2* aS = Ai + (size_t)(m0 + srow) * 512 + sp * 2;
    const uint2* bS = Bi + (size_t)(n0 + srow) * 512 + sp * 2;
    const u32 dAb = sb + srow * 64 + sp * 16;
    const u32 dBb = sb + 8192 + srow * 64 + sp * 16;

    float d[4][4][4];
#pragma unroll
    for (int mt = 0; mt < 4; mt++)
#pragma unroll
        for (int nt = 0; nt < 4; nt++)
#pragma unroll
            for (int e = 0; e < 4; e++) d[mt][nt][e] = 0.f;

#pragma unroll
    for (int c = 0; c < 3; c++) {
        const u32 off = c * 16384;
        CP16(dAb + off, aS + c * 8);
        CP16(dAb + off + 16, aS + c * 8 + 2);
        CP16(dBb + off, bS + c * 8);
        CP16(dBb + off + 16, bS + c * 8 + 2);
        CPC;
    }

    for (int c = 0; c < 64; c++) {
        CPW(2);
        __syncthreads();

        const uint4* A4 = dynsm4 + (c & 3) * 1024;
        const uint4* B4 = A4 + 512;

        u32 bh[4][2], bl[4][2];
#pragma unroll
        for (int nt = 0; nt < 4; nt++) {
            uint4 v = B4[(wn * 32 + nt * 8 + lq) * 4 + lr];
            bh[nt][0] = v.x; bh[nt][1] = v.z;
            bl[nt][0] = v.y; bl[nt][1] = v.w;
        }
#pragma unroll
        for (int mt = 0; mt < 4; mt++) {
            int row  = wm * 64 + mt * 16 + lq;
            uint4 v0 = A4[row * 4 + lr];
            uint4 v1 = A4[(row + 8) * 4 + lr];
            u32 ah[4] = {v0.x, v1.x, v0.z, v1.z};
            u32 al[4] = {v0.y, v1.y, v0.w, v1.w};
#pragma unroll
            for (int nt = 0; nt < 4; nt++) {
                mma16816(d[mt][nt], ah, bh[nt]);
                mma16816(d[mt][nt], ah, bl[nt]);
                mma16816(d[mt][nt], al, bh[nt]);
            }
        }

        if (c + 3 < 64) {
            const u32 off = ((c + 3) & 3) * 16384;
            CP16(dAb + off, aS + (c + 3) * 8);
            CP16(dAb + off + 16, aS + (c + 3) * 8 + 2);
            CP16(dBb + off, bS + (c + 3) * 8);
            CP16(dBb + off + 16, bS + (c + 3) * 8 + 2);
        }
        CPC;
    }

    // --- epilogue ---
#pragma unroll
    for (int mt = 0; mt < 4; mt++) {
#pragma unroll
        for (int nt = 0; nt < 4; nt++) {
            int m = m0 + wm * 64 + mt * 16 + lq;
            int n = n0 + wn * 32 + nt * 8 + lr * 2;
            float2 bv = *(const float2*)&bias[n];
            float o00 = d[mt][nt][0] + bv.x, o01 = d[mt][nt][1] + bv.y;
            float o10 = d[mt][nt][2] + bv.x, o11 = d[mt][nt][3] + bv.y;
            if (MODE == 1) {
                *(float2*)&outp[(size_t)m * 1024 + n]       = make_float2(o00, o01);
                *(float2*)&outp[(size_t)(m + 8) * 1024 + n] = make_float2(o10, o11);
            } else {
                int bb = m >> 11, ssq = m & 2047;
                int which = n >> 10;
                int head  = (n & 1023) >> 6;
                int hd    = n & 63;
                u32 h0, l0, h1, l1;
                split2(o00, o01, h0, l0);
                split2(o10, o11, h1, l1);
                if (which < 2) {
                    uint2* dst = (which == 0) ? d_Qi : d_Ki;
                    int p = hd >> 1;
                    size_t idx =
                        (((size_t)bb * HH + head) * SS + ssq) * 32 + kperm(p);
                    dst[idx]       = make_uint2(h0, l0);
                    dst[idx + 256] = make_uint2(h1, l1);
                } else {
                    // V^T interleaved {hi,lo} u32 per kpair, permuted.
                    // value (token m, feature hd): kpair p = m>>1 (lane m&1)
                    int p  = ssq >> 1;
                    int sl = 2 * kperm(p);  // hi u32 slot; lo at sl+1
                    int p8  = (ssq + 8) >> 1;
                    int sl8 = 2 * kperm(p8);
                    size_t r0 = (((size_t)bb * HH + head) * HD + hd) * 2 * SS;
                    size_t r1 = r0 + 2 * SS;  // feature hd+1
                    int ln = ssq & 1;
                    d_Vt[r0 + 2 * sl + ln]       = (u16)(h0 & 0xffff);
                    d_Vt[r0 + 2 * (sl + 1) + ln] = (u16)(l0 & 0xffff);
                    d_Vt[r1 + 2 * sl + ln]       = (u16)(h0 >> 16);
                    d_Vt[r1 + 2 * (sl + 1) + ln] = (u16)(l0 >> 16);
                    d_Vt[r0 + 2 * sl8 + ln]       = (u16)(h1 & 0xffff);
                    d_Vt[r0 + 2 * (sl8 + 1) + ln] = (u16)(l1 & 0xffff);
                    d_Vt[r1 + 2 * sl8 + ln]       = (u16)(h1 >> 16);
                    d_Vt[r1 + 2 * (sl8 + 1) + ln] = (u16)(l1 >> 16);
                }
            }
        }
    }
}

// ---------------------------------------------------------------------------
// Flash attention: 3-stage cp.async pipeline, one sync per tile,
// chunk-major [kc][row][4 uint4] smem (conflict-free LDS.128 frags).
// stage = K 16KB + V 16KB = 32KB; 3 stages = 96KB.
// ---------------------------------------------------------------------------
#define AT_SMEM (3 * 32768)

__global__ void __launch_bounds__(256, 2) attn_mma(const float* __restrict__ mask) {
    extern __shared__ uint4 atsm4[];
    const u32 sb = smem_u32(atsm4);

    const int tid  = threadIdx.x;
    const int wid  = tid >> 5, lane = tid & 31;
    const int lq   = lane >> 2, lr = lane & 3;
    const int qt = blockIdx.x, h = blockIdx.y, b = blockIdx.z;
    const size_t bh = (size_t)b * HH + h;
    const int q0 = qt * 128;
    const int qw = q0 + wid * 16;

    // ---- Q a-frags: 8 x LDG.128 from permuted gmem ----
    u32 qfh[4][4], qfl[4][4];
    {
        const uint4* Q4 = (const uint4*)d_Qi + (bh * SS + qw + lq) * 16;
#pragma unroll
        for (int kc = 0; kc < 4; kc++) {
            uint4 v0 = Q4[kc * 4 + lr];
            uint4 v1 = Q4[128 + kc * 4 + lr];  // row +8
            qfh[kc][0] = v0.x; qfh[kc][1] = v1.x; qfh[kc][2] = v0.z; qfh[kc][3] = v1.z;
            qfl[kc][0] = v0.y; qfl[kc][1] = v1.y; qfl[kc][2] = v0.w; qfl[kc][3] = v1.w;
        }
    }

    float o[8][4];
#pragma unroll
    for (int nt = 0; nt < 8; nt++)
#pragma unroll
        for (int e = 0; e < 4; e++) o[nt][e] = 0.f;
    float m0r = -1e30f, m1r = -1e30f, l0r = 0.f, l1r = 0.f;

    const float scale = 0.125f;
    const float* mp0 = mask + (size_t)(qw + lq) * SS;
    const float* mp1 = mask + (size_t)(qw + lq + 8) * SS;

    // staging coords: thread t -> chunk sc = t&3, row srw = t>>2
    const int sc  = tid & 3;
    const int srw = tid >> 2;
    const uint4* kS = (const uint4*)d_Ki + (bh * SS + srw) * 16 + sc * 4;
    const uint4* vS = (const uint4*)d_Vt + (bh * HD + srw) * 512 + sc * 4;
    const u32 dKs = sb + sc * 4096 + srw * 64;
    const u32 dVs = sb + 16384 + sc * 4096 + srw * 64;

    // prologue: stage tiles 0,1
#pragma unroll
    for (int t = 0; t < 2; t++) {
        const u32 off = t * 32768;
#pragma unroll
        for (int q = 0; q < 4; q++) {
            CP16(dKs + off + q * 16, kS + (size_t)t * 1024 + q);
            CP16(dVs + off + q * 16, vS + t * 16 + q);
        }
        CPC;
    }

    for (int kt = 0; kt < SS / 64; kt++) {
        const int k0 = kt * 64;
        CPW(1);
        __syncthreads();

        // stage tile kt+2 into buf (kt+2)%3 (readers done as of this sync)
        if (kt + 2 < SS / 64) {
            const u32 off = ((kt + 2) % 3) * 32768;
#pragma unroll
            for (int q = 0; q < 4; q++) {
                CP16(dKs + off + q * 16, kS + (size_t)(kt + 2) * 1024 + q);
                CP16(dVs + off + q * 16, vS + (kt + 2) * 16 + q);
            }
        }
        CPC;

        const uint4* K4 = atsm4 + (kt % 3) * 2048;
        const uint4* V4 = K4 + 1024;

        // ---- S = Q @ K^T ----
        float s[8][4];
#pragma unroll
        for (int nt = 0; nt < 8; nt++)
#pragma unroll
            for (int e = 0; e < 4; e++) s[nt][e] = 0.f;

#pragma unroll
        for (int kc = 0; kc < 4; kc++) {
#pragma unroll
            for (int nt = 0; nt < 8; nt++) {
                uint4 v = K4[kc * 256 + (nt * 8 + lq) * 4 + lr];
                u32 bhf[2] = {v.x, v.z};
                u32 blf[2] = {v.y, v.w};
                mma16816(s[nt], qfh[kc], bhf);
                mma16816(s[nt], qfh[kc], blf);
                mma16816(s[nt], qfl[kc], bhf);
            }
        }

        // ---- scale + mask ----
#pragma unroll
        for (int nt = 0; nt < 8; nt++) {
            float2 ma = *(const float2*)(mp0 + k0 + nt * 8 + 2 * lr);
            float2 mb = *(const float2*)(mp1 + k0 + nt * 8 + 2 * lr);
            s[nt][0] = s[nt][0] * scale + ma.x;
            s[nt][1] = s[nt][1] * scale + ma.y;
            s[nt][2] = s[nt][2] * scale + mb.x;
            s[nt][3] = s[nt][3] * scale + mb.y;
        }

        // ---- online softmax ----
        float r0 = -1e30f, r1 = -1e30f;
#pragma unroll
        for (int nt = 0; nt < 8; nt++) {
            r0 = fmaxf(r0, fmaxf(s[nt][0], s[nt][1]));
            r1 = fmaxf(r1, fmaxf(s[nt][2], s[nt][3]));
        }
        r0 = fmaxf(r0, __shfl_xor_sync(0xffffffffu, r0, 1));
        r0 = fmaxf(r0, __shfl_xor_sync(0xffffffffu, r0, 2));
        r1 = fmaxf(r1, __shfl_xor_sync(0xffffffffu, r1, 1));
        r1 = fmaxf(r1, __shfl_xor_sync(0xffffffffu, r1, 2));

        float nm0 = fmaxf(m0r, r0), nm1 = fmaxf(m1r, r1);
        float c0 = __expf(m0r - nm0), c1 = __expf(m1r - nm1);
        float sum0 = 0.f, sum1 = 0.f;
#pragma unroll
        for (int nt = 0; nt < 8; nt++) {
            s[nt][0] = __expf(s[nt][0] - nm0);
            s[nt][1] = __expf(s[nt][1] - nm0);
            s[nt][2] = __expf(s[nt][2] - nm1);
            s[nt][3] = __expf(s[nt][3] - nm1);
            sum0 += s[nt][0] + s[nt][1];
            sum1 += s[nt][2] + s[nt][3];
        }
        sum0 += __shfl_xor_sync(0xffffffffu, sum0, 1);
        sum0 += __shfl_xor_sync(0xffffffffu, sum0, 2);
        sum1 += __shfl_xor_sync(0xffffffffu, sum1, 1);
        sum1 += __shfl_xor_sync(0xffffffffu, sum1, 2);
        l0r = l0r * c0 + sum0;
        l1r = l1r * c1 + sum1;
        m0r = nm0; m1r = nm1;
#pragma unroll
        for (int nt = 0; nt < 8; nt++) {
            o[nt][0] *= c0; o[nt][1] *= c0;
            o[nt][2] *= c1; o[nt][3] *= c1;
        }

        // ---- O += P @ V ----
#pragma unroll
        for (int kc = 0; kc < 4; kc++) {
            u32 ph[4], pl[4];
            split2(s[2 * kc][0], s[2 * kc][1], ph[0], pl[0]);
            split2(s[2 * kc][2], s[2 * kc][3], ph[1], pl[1]);
            split2(s[2 * kc + 1][0], s[2 * kc + 1][1], ph[2], pl[2]);
            split2(s[2 * kc + 1][2], s[2 * kc + 1][3], ph[3], pl[3]);
#pragma unroll
            for (int nt = 0; nt < 8; nt++) {
                uint4 v = V4[kc * 256 + (nt * 8 + lq) * 4 + lr];
                u32 bhf[2] = {v.x, v.z};
                u32 blf[2] = {v.y, v.w};
                mma16816(o[nt], ph, bhf);
                mma16816(o[nt], ph, blf);
                mma16816(o[nt], pl, bhf);
            }
        }
    }

    // ---- epilogue: normalize, split, write ctx permuted ----
    float inv0 = 1.f / l0r, inv1 = 1.f / l1r;
    size_t r0c = ((size_t)b * SS + qw + lq) * 512 + h * 32;
    size_t r1c = r0c + 8 * 512;
#pragma unroll
    for (int nt = 0; nt < 8; nt++) {
        int pidx = (nt >> 1) * 8 + 2 * lr + (nt & 1);  // kperm of nt*4+lr
        u32 hh, ll;
        split2(o[nt][0] * inv0, o[nt][1] * inv0, hh, ll);
        d_Ci[r0c + pidx] = make_uint2(hh, ll);
        split2(o[nt][2] * inv1, o[nt][3] * inv1, hh, ll);
        d_Ci[r1c + pidx] = make_uint2(hh, ll);
    }
}

// ---------------------------------------------------------------------------
extern "C" void kernel_launch(void* const* d_in, const int* in_sizes, int n_in,
                              void* d_out, int out_size) {
    const float* x    = (const float*)d_in[0];
    const float* mask = (const float*)d_in[1];
    const float* Wqkv = (const float*)d_in[2];
    const float* bqkv = (const float*)d_in[3];
    const float* Wout = (const float*)d_in[4];
    const float* bout = (const float*)d_in[5];
    float*       out  = (float*)d_out;

    (void)in_sizes; (void)n_in; (void)out_size;

    uint2 *xi, *wqi, *woi, *ci;
    cudaGetSymbolAddress((void**)&xi, d_Xi);
    cudaGetSymbolAddress((void**)&wqi, d_Wqi);
    cudaGetSymbolAddress((void**)&woi, d_Woi);
    cudaGetSymbolAddress((void**)&ci, d_Ci);

    cudaFuncSetAttribute(mm_bf16<0>, cudaFuncAttributeMaxDynamicSharedMemorySize,
                         MM_SMEM);
    cudaFuncSetAttribute(mm_bf16<1>, cudaFuncAttributeMaxDynamicSharedMemorySize,
                         MM_SMEM);
    cudaFuncSetAttribute(attn_mma, cudaFuncAttributeMaxDynamicSharedMemorySize,
                         AT_SMEM);

    // 0) one-time splits (permuted layout)
    prep_x<<<4096, 256>>>(x);
    prep_wt<3072><<<dim3(3072 / 32, 16), dim3(32, 32)>>>(Wqkv, wqi);
    prep_wt<1024><<<dim3(1024 / 32, 16), dim3(32, 32)>>>(Wout, woi);

    // 1) QKV projection
    mm_bf16<0><<<dim3(3072 / 128, 8192 / 128), 256, MM_SMEM>>>(
        xi, wqi, bqkv, nullptr);

    // 2) attention
    attn_mma<<<dim3(SS / 128, HH, BB), 256, AT_SMEM>>>(mask);

    // 3) output projection
    mm_bf16<1><<<dim3(1024 / 128, 8192 / 128), 256, MM_SMEM>>>(
        ci, woi, bout, out);
}